// round 10
// baseline (speedup 1.0000x reference)
#include <cuda_runtime.h>
#include <cstdint>

#define B_DIM 512
#define N_DIM 16384
#define R_DIM 128
#define SPLITS 32
#define KSPAN (N_DIM / SPLITS)   // 512

// quantization scales: v ~= S*(h + l/252), h,l in [-126,126]
#define QS_X   15.75f            // 126/8      (|x| < 8)
#define QS_U   6300.0f           // 126/0.02
#define QS_P   15.75f            // 126/8      (|pre| < 8)
#define QS_V   6300.0f
#define SC1    ((8.0f / 126.0f) * (0.02f / 126.0f))   // S_X*S_U
#define SC1C   (SC1 / 252.0f)
#define SC2    ((8.0f / 126.0f) * (0.02f / 126.0f))   // S_P*S_V
#define SC2C   (SC2 / 252.0f)

__device__ float g_maskf[N_DIM];
__device__ float g_partial[SPLITS * B_DIM * R_DIM];   // [split][m][r], 8 MB
__device__ uint32_t g_phi[B_DIM * R_DIM / 4];         // pre hi-limb int8x4
__device__ uint32_t g_plo[B_DIM * R_DIM / 4];         // pre lo-limb
__device__ uint32_t g_vhi[N_DIM * R_DIM / 4];         // V hi-limb int8x4, 2 MB
__device__ uint32_t g_vlo[N_DIM * R_DIM / 4];         // V lo-limb

// ---------------- int8 2-limb quantization ----------------
__device__ __forceinline__ void quant1(float v, float invs, int& h, int& l) {
    float f = v * invs;
    float fc = fminf(fmaxf(f, -126.0f), 126.0f);
    h = __float2int_rn(fc);
    float r = (f - (float)h) * 252.0f;
    l = __float2int_rn(fminf(fmaxf(r, -127.0f), 127.0f));
}
__device__ __forceinline__ void quant4(float4 v, float invs, uint32_t& hq,
                                       uint32_t& lq) {
    int h0, l0, h1, l1, h2, l2, h3, l3;
    quant1(v.x, invs, h0, l0);
    quant1(v.y, invs, h1, l1);
    quant1(v.z, invs, h2, l2);
    quant1(v.w, invs, h3, l3);
    hq = (h0 & 255) | ((h1 & 255) << 8) | ((h2 & 255) << 16) | ((h3 & 255) << 24);
    lq = (l0 & 255) | ((l1 & 255) << 8) | ((l2 & 255) << 16) | ((l3 & 255) << 24);
}

__device__ __forceinline__ uint32_t smem_u32(const void* p) {
    uint32_t a;
    asm("{ .reg .u64 t; cvta.to.shared.u64 t, %1; cvt.u32.u64 %0, t; }"
        : "=r"(a) : "l"(p));
    return a;
}
__device__ __forceinline__ void ldsm_x4(uint32_t* r, uint32_t addr) {
    asm volatile("ldmatrix.sync.aligned.m8n8.x4.shared.b16 {%0,%1,%2,%3}, [%4];"
                 : "=r"(r[0]), "=r"(r[1]), "=r"(r[2]), "=r"(r[3]) : "r"(addr));
}
__device__ __forceinline__ void mma_s8(int* c, const uint32_t* a,
                                       const uint32_t* b) {
    asm volatile(
        "mma.sync.aligned.m16n8k32.row.col.s32.s8.s8.s32 "
        "{%0,%1,%2,%3}, {%4,%5,%6,%7}, {%8,%9}, {%0,%1,%2,%3};"
        : "+r"(c[0]), "+r"(c[1]), "+r"(c[2]), "+r"(c[3])
        : "r"(a[0]), "r"(a[1]), "r"(a[2]), "r"(a[3]), "r"(b[0]), "r"(b[1]));
}
__device__ __forceinline__ void cp16(uint32_t smem_addr, const void* gptr) {
    asm volatile("cp.async.cg.shared.global [%0], [%1], 16;"
                 :: "r"(smem_addr), "l"(gptr));
}
#define CP_COMMIT() asm volatile("cp.async.commit_group;" ::: "memory")
#define CP_WAIT0()  asm volatile("cp.async.wait_group 0;" ::: "memory")

// ---------------- generic int8 warp-tile MMA ----------------
// A tile rows m (k-contig int8), B tile rows n. LDKB = row stride bytes.
// Warp computes 32(M) x (NI*8)(N); per kstep of 32 int8.
template <int LDKB, int NKS, int NI>
__device__ __forceinline__ void tile_s8(uint32_t sb, int offAH, int offAL,
                                        int offBH, int offBL, int warp_m,
                                        int warp_n, int lane, int arowbase,
                                        int (&chh)[2][NI][4],
                                        int (&ccr)[2][NI][4]) {
#pragma unroll
    for (int ks = 0; ks < NKS; ks++) {
        uint32_t a[2][2][4];  // [mi][limb][4]
#pragma unroll
        for (int mi = 0; mi < 2; mi++) {
            uint32_t ro =
                (uint32_t)(arowbase + warp_m + mi * 16 + (lane & 15)) * LDKB +
                ks * 32 + ((lane >> 4) << 4);
            ldsm_x4(a[mi][0], sb + offAH + ro);
            ldsm_x4(a[mi][1], sb + offAL + ro);
        }
#pragma unroll
        for (int p = 0; p < NI / 2; p++) {
            uint32_t ro = (uint32_t)(warp_n + p * 16 + ((lane >> 4) << 3) +
                                     (lane & 7)) * LDKB +
                          ks * 32 + (((lane >> 3) & 1) << 4);
            uint32_t th[4], tl[4];
            ldsm_x4(th, sb + offBH + ro);
            ldsm_x4(tl, sb + offBL + ro);
#pragma unroll
            for (int mi = 0; mi < 2; mi++) {
                mma_s8(chh[mi][2 * p], a[mi][0], th);          // hh
                mma_s8(ccr[mi][2 * p], a[mi][0], tl);          // hl
                mma_s8(ccr[mi][2 * p], a[mi][1], th);          // lh
                mma_s8(chh[mi][2 * p + 1], a[mi][0], th + 2);
                mma_s8(ccr[mi][2 * p + 1], a[mi][0], tl + 2);
                mma_s8(ccr[mi][2 * p + 1], a[mi][1], th + 2);
            }
        }
    }
}

// =================== GEMM1: partial[split] = x_tile @ U_tile (int8) ========
// M=128, N=128(rank), KBLK=64 int8, NITER=8, 512 threads.
#define LDK1B 80
#define PL1 (128 * LDK1B)    // 10240
#define A1H 0
#define A1L PL1
#define B1H (2 * PL1)
#define B1L (3 * PL1)
#define BUF1 (4 * PL1)       // 40960
#define SMEM1 (2 * BUF1)     // 81920

__device__ __forceinline__ void g1_lq_a(const float* __restrict__ x, int m0,
                                        int k0, int tid, uint32_t* ah,
                                        uint32_t* al) {
#pragma unroll
    for (int rep = 0; rep < 4; rep++) {
        int p = rep * 512 + tid;
        int row = p >> 4, c4 = p & 15;
        float4 v = *(const float4*)(x + (size_t)(m0 + row) * N_DIM + k0 + c4 * 4);
        quant4(v, QS_X, ah[rep], al[rep]);
    }
}
__device__ __forceinline__ void g1_sts_a(char* smem, int buf, int tid,
                                         const uint32_t* ah,
                                         const uint32_t* al) {
#pragma unroll
    for (int rep = 0; rep < 4; rep++) {
        int p = rep * 512 + tid;
        int row = p >> 4, c4 = p & 15;
        uint32_t off = (uint32_t)(row * LDK1B + c4 * 4);
        *(uint32_t*)(smem + buf + A1H + off) = ah[rep];
        *(uint32_t*)(smem + buf + A1L + off) = al[rep];
    }
}
__device__ __forceinline__ void g1_lq_b(const float* __restrict__ U, int k0,
                                        int tid, uint32_t* bh, uint32_t* bl) {
    int n = tid & 127, kq = tid >> 7;
#pragma unroll
    for (int q = 0; q < 4; q++) {
        int k = q * 16 + kq * 4;
        const float* up = U + (size_t)(k0 + k) * R_DIM + n;
        float4 v;
        v.x = up[0];
        v.y = up[R_DIM];
        v.z = up[2 * R_DIM];
        v.w = up[3 * R_DIM];
        quant4(v, QS_U, bh[q], bl[q]);
    }
}
__device__ __forceinline__ void g1_sts_b(char* smem, int buf, int tid,
                                         const uint32_t* bh,
                                         const uint32_t* bl) {
    int n = tid & 127, kq = tid >> 7;
#pragma unroll
    for (int q = 0; q < 4; q++) {
        int k = q * 16 + kq * 4;
        uint32_t off = (uint32_t)(n * LDK1B + k);
        *(uint32_t*)(smem + buf + B1H + off) = bh[q];
        *(uint32_t*)(smem + buf + B1L + off) = bl[q];
    }
}

__global__ __launch_bounds__(512) void gemm1_mma(const float* __restrict__ x,
                                                 const float* __restrict__ U) {
    extern __shared__ char smem[];
    const int tid = threadIdx.x, wid = tid >> 5, lane = tid & 31;
    const int warp_m = (wid & 3) * 32, warp_n = (wid >> 2) * 32;
    const int m0 = blockIdx.x * 128;
    const int split = blockIdx.y;
    const int kbase = split * KSPAN;
    const uint32_t sb = smem_u32(smem);

    int chh[2][4][4], ccr[2][4][4];
#pragma unroll
    for (int mi = 0; mi < 2; mi++)
#pragma unroll
        for (int ni = 0; ni < 4; ni++)
#pragma unroll
            for (int j = 0; j < 4; j++) { chh[mi][ni][j] = 0; ccr[mi][ni][j] = 0; }

    {
        uint32_t ah[4], al[4], bh[4], bl[4];
        g1_lq_a(x, m0, kbase, tid, ah, al);
        g1_lq_b(U, kbase, tid, bh, bl);
        g1_sts_a(smem, 0, tid, ah, al);
        g1_sts_b(smem, 0, tid, bh, bl);
    }
    __syncthreads();

    const int NITER = KSPAN / 64;  // 8
    for (int it = 0; it < NITER; it++) {
        const int cur = (it & 1) * BUF1;
        const int nxt = ((it + 1) & 1) * BUF1;
        uint32_t ah[4], al[4], bh[4], bl[4];
        if (it + 1 < NITER) {
            g1_lq_a(x, m0, kbase + (it + 1) * 64, tid, ah, al);
            g1_lq_b(U, kbase + (it + 1) * 64, tid, bh, bl);
        }
        tile_s8<LDK1B, 2, 4>(sb, cur + A1H, cur + A1L, cur + B1H, cur + B1L,
                             warp_m, warp_n, lane, 0, chh, ccr);
        if (it + 1 < NITER) {
            g1_sts_a(smem, nxt, tid, ah, al);
            g1_sts_b(smem, nxt, tid, bh, bl);
        }
        __syncthreads();
    }

    float* base = g_partial + (size_t)split * (B_DIM * R_DIM);
#pragma unroll
    for (int mi = 0; mi < 2; mi++) {
        int row0 = m0 + warp_m + mi * 16 + (lane >> 2);
#pragma unroll
        for (int ni = 0; ni < 4; ni++) {
            int col = warp_n + ni * 8 + (lane & 3) * 2;
            float v0 = (float)chh[mi][ni][0] * SC1 + (float)ccr[mi][ni][0] * SC1C;
            float v1 = (float)chh[mi][ni][1] * SC1 + (float)ccr[mi][ni][1] * SC1C;
            float v2 = (float)chh[mi][ni][2] * SC1 + (float)ccr[mi][ni][2] * SC1C;
            float v3 = (float)chh[mi][ni][3] * SC1 + (float)ccr[mi][ni][3] * SC1C;
            *(float2*)(base + (size_t)row0 * R_DIM + col) = make_float2(v0, v1);
            *(float2*)(base + (size_t)(row0 + 8) * R_DIM + col) =
                make_float2(v2, v3);
        }
    }
}

// ============ prep2: V quantize + mask zero + partial reduce->pre quantize ==
__global__ void prep2_kernel(const float* __restrict__ V) {
    const int b = blockIdx.x, tid = threadIdx.x;
    if (b < 2048) {  // V quant: 524288 float4s
        int i = b * 256 + tid;
        float4 v = *(const float4*)(V + (size_t)i * 4);
        uint32_t h, l;
        quant4(v, QS_V, h, l);
        g_vhi[i] = h;
        g_vlo[i] = l;
    } else if (b < 2064) {  // mask zero: 4096 float4s
        int i = (b - 2048) * 256 + tid;
        *(float4*)(g_maskf + (size_t)i * 4) = make_float4(0.f, 0.f, 0.f, 0.f);
    } else {  // reduce: 16384 float4s over 32 splits, 8-wide MLP batches
        int i = (b - 2064) * 256 + tid;
        float4 s = make_float4(0.f, 0.f, 0.f, 0.f);
#pragma unroll
        for (int g = 0; g < 4; g++) {
            float4 v[8];
#pragma unroll
            for (int j = 0; j < 8; j++)
                v[j] = *(const float4*)(g_partial +
                                        (size_t)(g * 8 + j) * (B_DIM * R_DIM) +
                                        (size_t)i * 4);
#pragma unroll
            for (int j = 0; j < 8; j++) {
                s.x += v[j].x; s.y += v[j].y; s.z += v[j].z; s.w += v[j].w;
            }
        }
        uint32_t h, l;
        quant4(s, QS_P, h, l);
        g_phi[i] = h;
        g_plo[i] = l;
    }
}

__global__ void scatter_mask_kernel(const int* __restrict__ idx, int nnz) {
    for (int i = blockIdx.x * blockDim.x + threadIdx.x; i < nnz;
         i += gridDim.x * blockDim.x) {
        int j = idx[i];
        if (j >= 0 && j < N_DIM) g_maskf[j] = 1.0f;
    }
}

// ============ GEMM2: out = mask .* (pre @ V^T), persistent smem, int8 =======
// CTA: B 256 n-rows x K=128 + A 256 m-rows x K=128 (both 2 limbs), loaded once
// via cp.async; compute phase barrier-free. Grid (64, 2).
#define LDK2B 144
#define PB2 (256 * LDK2B)   // 36864 per plane
#define O2BH 0
#define O2BL PB2
#define O2AH (2 * PB2)
#define O2AL (3 * PB2)
#define SMEM2 (4 * PB2)     // 147456

__global__ __launch_bounds__(512) void gemm2_mma(float* __restrict__ out) {
    extern __shared__ char smem[];
    const int tid = threadIdx.x, wid = tid >> 5, lane = tid & 31;
    const int n0 = blockIdx.x * 256;
    const int mbase = blockIdx.y * 256;
    const uint32_t sb = smem_u32(smem);

    // load B limbs (256 rows x 128B) and A limbs (256 rows x 128B)
#pragma unroll
    for (int rep = 0; rep < 4; rep++) {
        int p = rep * 512 + tid;
        int row = p >> 3, kc = p & 7;
        cp16(sb + O2BH + (uint32_t)(row * LDK2B + kc * 16),
             (const char*)g_vhi + (size_t)(n0 + row) * R_DIM + kc * 16);
        cp16(sb + O2BL + (uint32_t)(row * LDK2B + kc * 16),
             (const char*)g_vlo + (size_t)(n0 + row) * R_DIM + kc * 16);
        cp16(sb + O2AH + (uint32_t)(row * LDK2B + kc * 16),
             (const char*)g_phi + (size_t)(mbase + row) * R_DIM + kc * 16);
        cp16(sb + O2AL + (uint32_t)(row * LDK2B + kc * 16),
             (const char*)g_plo + (size_t)(mbase + row) * R_DIM + kc * 16);
    }
    CP_COMMIT();
    CP_WAIT0();
    __syncthreads();

    const int wm = (wid & 3) * 32;
#pragma unroll
    for (int mt = 0; mt < 2; mt++) {
#pragma unroll
        for (int nh = 0; nh < 2; nh++) {
            const int wn = (wid >> 2) * 64 + nh * 32;
            int chh[2][4][4], ccr[2][4][4];
#pragma unroll
            for (int mi = 0; mi < 2; mi++)
#pragma unroll
                for (int ni = 0; ni < 4; ni++)
#pragma unroll
                    for (int j = 0; j < 4; j++) {
                        chh[mi][ni][j] = 0;
                        ccr[mi][ni][j] = 0;
                    }

            tile_s8<LDK2B, 4, 4>(sb, O2AH, O2AL, O2BH, O2BL, wm, wn, lane,
                                 mt * 128, chh, ccr);

#pragma unroll
            for (int mi = 0; mi < 2; mi++) {
                int row0 = mbase + mt * 128 + wm + mi * 16 + (lane >> 2);
#pragma unroll
                for (int ni = 0; ni < 4; ni++) {
                    int col = n0 + wn + ni * 8 + (lane & 3) * 2;
                    float2 mk = *(const float2*)(g_maskf + col);
                    float v0 =
                        (float)chh[mi][ni][0] * SC2 + (float)ccr[mi][ni][0] * SC2C;
                    float v1 =
                        (float)chh[mi][ni][1] * SC2 + (float)ccr[mi][ni][1] * SC2C;
                    float v2 =
                        (float)chh[mi][ni][2] * SC2 + (float)ccr[mi][ni][2] * SC2C;
                    float v3 =
                        (float)chh[mi][ni][3] * SC2 + (float)ccr[mi][ni][3] * SC2C;
                    *(float2*)(out + (size_t)row0 * N_DIM + col) =
                        make_float2(v0 * mk.x, v1 * mk.y);
                    *(float2*)(out + (size_t)(row0 + 8) * N_DIM + col) =
                        make_float2(v2 * mk.x, v3 * mk.y);
                }
            }
        }
    }
}

// ---------------- launch ----------------
extern "C" void kernel_launch(void* const* d_in, const int* in_sizes, int n_in,
                              void* d_out, int out_size) {
    const float* x = (const float*)d_in[0];    // [512, 16384]
    const float* U = (const float*)d_in[1];    // [16384, 128]
    const float* V = (const float*)d_in[2];    // [16384, 128]
    const int* indices = (const int*)d_in[4];  // int32
    const int nnz = in_sizes[4];
    float* out = (float*)d_out;                // [512, 16384]

    cudaFuncSetAttribute(gemm1_mma, cudaFuncAttributeMaxDynamicSharedMemorySize,
                         SMEM1);
    cudaFuncSetAttribute(gemm2_mma, cudaFuncAttributeMaxDynamicSharedMemorySize,
                         SMEM2);

    gemm1_mma<<<dim3(B_DIM / 128, SPLITS), 512, SMEM1>>>(x, U);
    prep2_kernel<<<2128, 256>>>(V);
    scatter_mask_kernel<<<256, 256>>>(indices, nnz);
    gemm2_mma<<<dim3(N_DIM / 256, B_DIM / 256), 512, SMEM2>>>(out);
}